// round 12
// baseline (speedup 1.0000x reference)
#include <cuda_runtime.h>
#include <cstdint>

#define N_LEVELS 16
#define TABLE_SIZE (1u << 19)
#define TMASK (TABLE_SIZE - 1u)
#define P1 2654435761u
#define P2 805459861u
#define BLOCK 128
#define MAXN 2000000
#define GBITS 6
#define GRES (1 << GBITS)            // 64 cells per dim
#define NCELLS (GRES * GRES * GRES)  // 262144
#define S1_T 1024
#define S1_B (NCELLS / S1_T)         // 256

using ull = unsigned long long;

__device__ __forceinline__ ull pack2(float lo, float hi) {
    ull r; asm("mov.b64 %0, {%1, %2};" : "=l"(r) : "f"(lo), "f"(hi)); return r;
}
__device__ __forceinline__ void unpack2(ull v, float& lo, float& hi) {
    asm("mov.b64 {%0, %1}, %2;" : "=f"(lo), "=f"(hi) : "l"(v));
}
__device__ __forceinline__ ull fma2(ull a, ull b, ull c) {
    ull d; asm("fma.rn.f32x2 %0, %1, %2, %3;" : "=l"(d) : "l"(a), "l"(b), "l"(c)); return d;
}

// ---- static scratch (no allocation) ----
__device__ int    d_hist[NCELLS];
__device__ int    d_offs[NCELLS];   // after scan1: exclusive WITHIN scan1-block
__device__ int    d_bsum[S1_B];
__device__ int    d_boff[S1_B];     // exclusive scan of block totals
__device__ float4 d_xs[MAXN];       // bucket-sorted: (x01, y01, z01, bits(orig_idx))

__device__ __forceinline__ unsigned part1by2(unsigned v) {
    v &= 0x3FFu;
    v = (v | (v << 16)) & 0x030000FFu;
    v = (v | (v << 8))  & 0x0300F00Fu;
    v = (v | (v << 4))  & 0x030C30C3u;
    v = (v | (v << 2))  & 0x09249249u;
    return v;
}

__device__ __forceinline__ int cell_of(float x0, float x1, float x2) {
    unsigned cx = min(GRES - 1, (int)(x0 * (float)GRES));
    unsigned cy = min(GRES - 1, (int)(x1 * (float)GRES));
    unsigned cz = min(GRES - 1, (int)(x2 * (float)GRES));
    return (int)((part1by2(cx) << 2) | (part1by2(cy) << 1) | part1by2(cz));
}

__global__ void k_zero() {
    int i = blockIdx.x * blockDim.x + threadIdx.x;
    if (i < NCELLS) d_hist[i] = 0;
}

__global__ void k_hist(const float* __restrict__ x, int n) {
    int i = blockIdx.x * blockDim.x + threadIdx.x;
    if (i >= n) return;
    float x0 = x[3 * i + 0] * 0.5f + 0.5f;
    float x1 = x[3 * i + 1] * 0.5f + 0.5f;
    float x2 = x[3 * i + 2] * 0.5f + 0.5f;
    atomicAdd(&d_hist[cell_of(x0, x1, x2)], 1);
}

// phase 1: per-block scan of 1024 consecutive cells (coalesced)
__global__ void k_scan1() {
    __shared__ int sc[S1_T];
    const int t = threadIdx.x;
    const int g = blockIdx.x * S1_T + t;
    const int v = d_hist[g];
    sc[t] = v;
    __syncthreads();
    #pragma unroll
    for (int d = 1; d < S1_T; d <<= 1) {
        int u = (t >= d) ? sc[t - d] : 0;
        __syncthreads();
        sc[t] += u;
        __syncthreads();
    }
    d_offs[g] = sc[t] - v;                 // exclusive within block
    if (t == S1_T - 1) d_bsum[blockIdx.x] = sc[t];
}

// phase 2: exclusive scan of the 256 block totals
__global__ void k_scan2() {
    __shared__ int sc[S1_B];
    const int t = threadIdx.x;
    const int v = d_bsum[t];
    sc[t] = v;
    __syncthreads();
    #pragma unroll
    for (int d = 1; d < S1_B; d <<= 1) {
        int u = (t >= d) ? sc[t - d] : 0;
        __syncthreads();
        sc[t] += u;
        __syncthreads();
    }
    d_boff[t] = sc[t] - v;
}

// scatter adds the block offset inline (scan3 folded in)
__global__ void k_scatter(const float* __restrict__ x, int n) {
    int i = blockIdx.x * blockDim.x + threadIdx.x;
    if (i >= n) return;
    float x0 = x[3 * i + 0] * 0.5f + 0.5f;
    float x1 = x[3 * i + 1] * 0.5f + 0.5f;
    float x2 = x[3 * i + 2] * 0.5f + 0.5f;
    const int c = cell_of(x0, x1, x2);
    int pos = atomicAdd(&d_offs[c], 1) + d_boff[c >> 10];
    d_xs[pos] = make_float4(x0, x1, x2, __int_as_float(i));
}

__global__ __launch_bounds__(BLOCK, 4)
void hashgrid_mlp_kernel(const float* __restrict__ tables,
                         const float* __restrict__ resolutions,
                         const float* __restrict__ W1, const float* __restrict__ b1,
                         const float* __restrict__ W2, const float* __restrict__ b2,
                         const float* __restrict__ W3, const float* __restrict__ b3,
                         float* __restrict__ out, int n)
{
    __shared__ __align__(16) float sW1[32 * 64];
    __shared__ __align__(16) float sW2[64 * 64];
    __shared__ __align__(16) float sB1[64];
    __shared__ __align__(16) float sB2[64];
    __shared__ __align__(16) float sW3[64];
    __shared__ float sRes[16];
    __shared__ float sB3;

    const int tid = threadIdx.x;
    for (int i = tid; i < 32 * 64; i += BLOCK) sW1[i] = W1[i];
    for (int i = tid; i < 64 * 64; i += BLOCK) sW2[i] = W2[i];
    if (tid < 64) { sB1[tid] = b1[tid]; sB2[tid] = b2[tid]; sW3[tid] = W3[tid]; }
    if (tid < 16) sRes[tid] = resolutions[tid];
    if (tid == 0) sB3 = b3[0];
    __syncthreads();

    const int p = blockIdx.x * BLOCK + tid;
    if (p >= n) return;

    const float4 xi = d_xs[p];            // coalesced; Morton-bucket-sorted point
    const float x0 = xi.x, x1 = xi.y, x2 = xi.z;
    const int oidx = __float_as_int(xi.w);

    float a[2 * N_LEVELS];

    #pragma unroll
    for (int L = 0; L < N_LEVELS; L++) {
        const float r = sRes[L];
        const float px = x0 * r, py = x1 * r, pz = x2 * r;
        const float fx = floorf(px), fy = floorf(py), fz = floorf(pz);
        const float wx = px - fx, wy = py - fy, wz = pz - fz;
        const unsigned cx = (unsigned)fx, cy = (unsigned)fy, cz = (unsigned)fz;

        const unsigned hx0 = cx,        hx1 = cx + 1u;
        const unsigned hy0 = cy * P1,   hy1 = (cy + 1u) * P1;
        const unsigned hz0 = cz * P2,   hz1 = (cz + 1u) * P2;

        const float2* __restrict__ tab =
            reinterpret_cast<const float2*>(tables) + (size_t)L * TABLE_SIZE;

        const float ox = 1.0f - wx, oy = 1.0f - wy, oz = 1.0f - wz;

        float ax = 0.0f, ay = 0.0f;
        #pragma unroll
        for (int c = 0; c < 8; c++) {
            const unsigned h = ((c & 1) ? hx1 : hx0)
                             ^ ((c & 2) ? hy1 : hy0)
                             ^ ((c & 4) ? hz1 : hz0);
            const unsigned idx = h & TMASK;
            const float2 t = __ldg(&tab[idx]);
            const float wc = ((c & 1) ? wx : ox)
                           * ((c & 2) ? wy : oy)
                           * ((c & 4) ? wz : oz);
            ax = fmaf(wc, t.x, ax);
            ay = fmaf(wc, t.y, ay);
        }
        a[2 * L + 0] = ax;
        a[2 * L + 1] = ay;
    }

    // ---- layer 1: [32] -> [64] packed as 32 f32x2 pairs over j ----
    ull h1p[32];
    #pragma unroll
    for (int j = 0; j < 32; j++)
        h1p[j] = *reinterpret_cast<const ull*>(&sB1[2 * j]);

    #pragma unroll
    for (int i = 0; i < 32; i++) {
        const ull ap = pack2(a[i], a[i]);
        const ull* wrow = reinterpret_cast<const ull*>(&sW1[i * 64]);
        #pragma unroll
        for (int j = 0; j < 32; j += 2) {
            const ulonglong2 w = *reinterpret_cast<const ulonglong2*>(&wrow[j]);
            h1p[j + 0] = fma2(ap, w.x, h1p[j + 0]);
            h1p[j + 1] = fma2(ap, w.y, h1p[j + 1]);
        }
    }

    // ---- layer 2: [64] -> [64] (packed over j, two halves), fused layer 3 ----
    float r3 = sB3;
    #pragma unroll
    for (int half = 0; half < 2; half++) {
        const int cb = 32 * half;
        ull acc[16];
        #pragma unroll
        for (int jj = 0; jj < 16; jj++)
            acc[jj] = *reinterpret_cast<const ull*>(&sB2[cb + 2 * jj]);

        #pragma unroll
        for (int i2 = 0; i2 < 32; i2++) {
            float lo, hi;
            unpack2(h1p[i2], lo, hi);
            lo = fmaxf(lo, 0.0f);
            hi = fmaxf(hi, 0.0f);
            const ull plo = pack2(lo, lo);
            const ull phi = pack2(hi, hi);
            const ull* w0 = reinterpret_cast<const ull*>(&sW2[(2 * i2 + 0) * 64 + cb]);
            const ull* w1 = reinterpret_cast<const ull*>(&sW2[(2 * i2 + 1) * 64 + cb]);
            #pragma unroll
            for (int jj = 0; jj < 16; jj += 2) {
                const ulonglong2 wa = *reinterpret_cast<const ulonglong2*>(&w0[jj]);
                acc[jj + 0] = fma2(plo, wa.x, acc[jj + 0]);
                acc[jj + 1] = fma2(plo, wa.y, acc[jj + 1]);
            }
            #pragma unroll
            for (int jj = 0; jj < 16; jj += 2) {
                const ulonglong2 wb = *reinterpret_cast<const ulonglong2*>(&w1[jj]);
                acc[jj + 0] = fma2(phi, wb.x, acc[jj + 0]);
                acc[jj + 1] = fma2(phi, wb.y, acc[jj + 1]);
            }
        }
        #pragma unroll
        for (int jj = 0; jj < 16; jj++) {
            float a0, a1;
            unpack2(acc[jj], a0, a1);
            r3 = fmaf(fmaxf(a0, 0.0f), sW3[cb + 2 * jj + 0], r3);
            r3 = fmaf(fmaxf(a1, 0.0f), sW3[cb + 2 * jj + 1], r3);
        }
    }

    out[oidx] = r3;
}

extern "C" void kernel_launch(void* const* d_in, const int* in_sizes, int n_in,
                              void* d_out, int out_size)
{
    const float* x    = (const float*)d_in[0];
    const float* tabs = (const float*)d_in[1];
    const float* res  = (const float*)d_in[2];
    const float* W1   = (const float*)d_in[3];
    const float* b1   = (const float*)d_in[4];
    const float* W2   = (const float*)d_in[5];
    const float* b2   = (const float*)d_in[6];
    const float* W3   = (const float*)d_in[7];
    const float* b3   = (const float*)d_in[8];
    float* out = (float*)d_out;

    const int n = in_sizes[0] / 3;

    k_zero<<<(NCELLS + 1023) / 1024, 1024>>>();
    k_hist<<<(n + 255) / 256, 256>>>(x, n);
    k_scan1<<<S1_B, S1_T>>>();
    k_scan2<<<1, S1_B>>>();
    k_scatter<<<(n + 255) / 256, 256>>>(x, n);

    const int grid = (n + BLOCK - 1) / BLOCK;
    hashgrid_mlp_kernel<<<grid, BLOCK>>>(tabs, res, W1, b1, W2, b2, W3, b3, out, n);
}

// round 13
// speedup vs baseline: 1.6156x; 1.6156x over previous
#include <cuda_runtime.h>
#include <cstdint>

#define N_LEVELS 16
#define TABLE_SIZE (1u << 19)
#define TMASK (TABLE_SIZE - 1u)
#define P1 2654435761u
#define P2 805459861u
#define BLOCK 128
#define MAXN 2000000
#define GBITS 6
#define GRES (1 << GBITS)            // 64 cells per dim
#define NCELLS (GRES * GRES * GRES)  // 262144
#define S1_T 1024
#define S1_B (NCELLS / S1_T)         // 256

using ull = unsigned long long;

__device__ __forceinline__ ull pack2(float lo, float hi) {
    ull r; asm("mov.b64 %0, {%1, %2};" : "=l"(r) : "f"(lo), "f"(hi)); return r;
}
__device__ __forceinline__ void unpack2(ull v, float& lo, float& hi) {
    asm("mov.b64 {%0, %1}, %2;" : "=f"(lo), "=f"(hi) : "l"(v));
}
__device__ __forceinline__ ull fma2(ull a, ull b, ull c) {
    ull d; asm("fma.rn.f32x2 %0, %1, %2, %3;" : "=l"(d) : "l"(a), "l"(b), "l"(c)); return d;
}

// ---- static scratch (no allocation) ----
__device__ int    d_hist[NCELLS];
__device__ int    d_offs[NCELLS];
__device__ int    d_bsum[S1_B];
__device__ int    d_boff[S1_B];
__device__ float4 d_xs[MAXN];   // bucket-sorted: (x01, y01, z01, bits(orig_idx))

// Morton: interleave 2 zero bits between bits of v
__device__ __forceinline__ unsigned part1by2(unsigned v) {
    v &= 0x3FFu;
    v = (v | (v << 16)) & 0x030000FFu;
    v = (v | (v << 8))  & 0x0300F00Fu;
    v = (v | (v << 4))  & 0x030C30C3u;
    v = (v | (v << 2))  & 0x09249249u;
    return v;
}

__device__ __forceinline__ int cell_of(float x0, float x1, float x2) {
    unsigned cx = min(GRES - 1, (int)(x0 * (float)GRES));
    unsigned cy = min(GRES - 1, (int)(x1 * (float)GRES));
    unsigned cz = min(GRES - 1, (int)(x2 * (float)GRES));
    return (int)((part1by2(cx) << 2) | (part1by2(cy) << 1) | part1by2(cz));
}

__global__ void k_zero() {
    int i = blockIdx.x * blockDim.x + threadIdx.x;
    if (i < NCELLS) d_hist[i] = 0;
}

__global__ void k_hist(const float* __restrict__ x, int n) {
    int i = blockIdx.x * blockDim.x + threadIdx.x;
    if (i >= n) return;
    float x0 = x[3 * i + 0] * 0.5f + 0.5f;
    float x1 = x[3 * i + 1] * 0.5f + 0.5f;
    float x2 = x[3 * i + 2] * 0.5f + 0.5f;
    atomicAdd(&d_hist[cell_of(x0, x1, x2)], 1);
}

// phase 1: per-block scan of 1024 consecutive cells (coalesced), exclusive
// within block; block total -> d_bsum
__global__ void k_scan1() {
    __shared__ int sc[S1_T];
    const int t = threadIdx.x;
    const int g = blockIdx.x * S1_T + t;
    const int v = d_hist[g];
    sc[t] = v;
    __syncthreads();
    #pragma unroll
    for (int d = 1; d < S1_T; d <<= 1) {
        int u = (t >= d) ? sc[t - d] : 0;
        __syncthreads();
        sc[t] += u;
        __syncthreads();
    }
    d_offs[g] = sc[t] - v;                 // exclusive within block
    if (t == S1_T - 1) d_bsum[blockIdx.x] = sc[t];
}

// phase 2: exclusive scan of the 256 block totals
__global__ void k_scan2() {
    __shared__ int sc[S1_B];
    const int t = threadIdx.x;
    const int v = d_bsum[t];
    sc[t] = v;
    __syncthreads();
    #pragma unroll
    for (int d = 1; d < S1_B; d <<= 1) {
        int u = (t >= d) ? sc[t - d] : 0;
        __syncthreads();
        sc[t] += u;
        __syncthreads();
    }
    d_boff[t] = sc[t] - v;
}

// phase 3: add block offsets (coalesced)
__global__ void k_scan3() {
    const int g = blockIdx.x * S1_T + threadIdx.x;
    d_offs[g] += d_boff[blockIdx.x];
}

__global__ void k_scatter(const float* __restrict__ x, int n) {
    int i = blockIdx.x * blockDim.x + threadIdx.x;
    if (i >= n) return;
    float x0 = x[3 * i + 0] * 0.5f + 0.5f;
    float x1 = x[3 * i + 1] * 0.5f + 0.5f;
    float x2 = x[3 * i + 2] * 0.5f + 0.5f;
    int pos = atomicAdd(&d_offs[cell_of(x0, x1, x2)], 1);
    d_xs[pos] = make_float4(x0, x1, x2, __int_as_float(i));
}

__global__ __launch_bounds__(BLOCK, 4)
void hashgrid_mlp_kernel(const float* __restrict__ tables,
                         const float* __restrict__ resolutions,
                         const float* __restrict__ W1, const float* __restrict__ b1,
                         const float* __restrict__ W2, const float* __restrict__ b2,
                         const float* __restrict__ W3, const float* __restrict__ b3,
                         float* __restrict__ out, int n)
{
    __shared__ __align__(16) float sW1[32 * 64];
    __shared__ __align__(16) float sW2[64 * 64];
    __shared__ __align__(16) float sB1[64];
    __shared__ __align__(16) float sB2[64];
    __shared__ __align__(16) float sW3[64];
    __shared__ float sRes[16];
    __shared__ float sB3;

    const int tid = threadIdx.x;
    for (int i = tid; i < 32 * 64; i += BLOCK) sW1[i] = W1[i];
    for (int i = tid; i < 64 * 64; i += BLOCK) sW2[i] = W2[i];
    if (tid < 64) { sB1[tid] = b1[tid]; sB2[tid] = b2[tid]; sW3[tid] = W3[tid]; }
    if (tid < 16) sRes[tid] = resolutions[tid];
    if (tid == 0) sB3 = b3[0];
    __syncthreads();

    const int p = blockIdx.x * BLOCK + tid;
    if (p >= n) return;

    const float4 xi = d_xs[p];            // coalesced; Morton-bucket-sorted point
    const float x0 = xi.x, x1 = xi.y, x2 = xi.z;
    const int oidx = __float_as_int(xi.w);

    float a[2 * N_LEVELS];

    #pragma unroll
    for (int L = 0; L < N_LEVELS; L++) {
        const float r = sRes[L];
        const float px = x0 * r, py = x1 * r, pz = x2 * r;
        const float fx = floorf(px), fy = floorf(py), fz = floorf(pz);
        const float wx = px - fx, wy = py - fy, wz = pz - fz;
        const unsigned cx = (unsigned)fx, cy = (unsigned)fy, cz = (unsigned)fz;

        const unsigned hx0 = cx,        hx1 = cx + 1u;
        const unsigned hy0 = cy * P1,   hy1 = (cy + 1u) * P1;
        const unsigned hz0 = cz * P2,   hz1 = (cz + 1u) * P2;

        const float2* __restrict__ tab =
            reinterpret_cast<const float2*>(tables) + (size_t)L * TABLE_SIZE;

        const float ox = 1.0f - wx, oy = 1.0f - wy, oz = 1.0f - wz;

        float ax = 0.0f, ay = 0.0f;
        #pragma unroll
        for (int c = 0; c < 8; c++) {
            const unsigned h = ((c & 1) ? hx1 : hx0)
                             ^ ((c & 2) ? hy1 : hy0)
                             ^ ((c & 4) ? hz1 : hz0);
            const unsigned idx = h & TMASK;
            const float2 t = __ldg(&tab[idx]);
            const float wc = ((c & 1) ? wx : ox)
                           * ((c & 2) ? wy : oy)
                           * ((c & 4) ? wz : oz);
            ax = fmaf(wc, t.x, ax);
            ay = fmaf(wc, t.y, ay);
        }
        a[2 * L + 0] = ax;
        a[2 * L + 1] = ay;
    }

    // ---- layer 1: [32] -> [64] packed as 32 f32x2 pairs over j ----
    ull h1p[32];
    #pragma unroll
    for (int j = 0; j < 32; j++)
        h1p[j] = *reinterpret_cast<const ull*>(&sB1[2 * j]);

    #pragma unroll
    for (int i = 0; i < 32; i++) {
        const ull ap = pack2(a[i], a[i]);
        const ull* wrow = reinterpret_cast<const ull*>(&sW1[i * 64]);
        #pragma unroll
        for (int j = 0; j < 32; j += 2) {
            const ulonglong2 w = *reinterpret_cast<const ulonglong2*>(&wrow[j]);
            h1p[j + 0] = fma2(ap, w.x, h1p[j + 0]);
            h1p[j + 1] = fma2(ap, w.y, h1p[j + 1]);
        }
    }

    // ---- layer 2: [64] -> [64] (packed over j, two halves), fused layer 3 ----
    float r3 = sB3;
    #pragma unroll
    for (int half = 0; half < 2; half++) {
        const int cb = 32 * half;
        ull acc[16];
        #pragma unroll
        for (int jj = 0; jj < 16; jj++)
            acc[jj] = *reinterpret_cast<const ull*>(&sB2[cb + 2 * jj]);

        #pragma unroll
        for (int i2 = 0; i2 < 32; i2++) {
            float lo, hi;
            unpack2(h1p[i2], lo, hi);
            lo = fmaxf(lo, 0.0f);
            hi = fmaxf(hi, 0.0f);
            const ull plo = pack2(lo, lo);
            const ull phi = pack2(hi, hi);
            const ull* w0 = reinterpret_cast<const ull*>(&sW2[(2 * i2 + 0) * 64 + cb]);
            const ull* w1 = reinterpret_cast<const ull*>(&sW2[(2 * i2 + 1) * 64 + cb]);
            #pragma unroll
            for (int jj = 0; jj < 16; jj += 2) {
                const ulonglong2 wa = *reinterpret_cast<const ulonglong2*>(&w0[jj]);
                acc[jj + 0] = fma2(plo, wa.x, acc[jj + 0]);
                acc[jj + 1] = fma2(plo, wa.y, acc[jj + 1]);
            }
            #pragma unroll
            for (int jj = 0; jj < 16; jj += 2) {
                const ulonglong2 wb = *reinterpret_cast<const ulonglong2*>(&w1[jj]);
                acc[jj + 0] = fma2(phi, wb.x, acc[jj + 0]);
                acc[jj + 1] = fma2(phi, wb.y, acc[jj + 1]);
            }
        }
        #pragma unroll
        for (int jj = 0; jj < 16; jj++) {
            float a0, a1;
            unpack2(acc[jj], a0, a1);
            r3 = fmaf(fmaxf(a0, 0.0f), sW3[cb + 2 * jj + 0], r3);
            r3 = fmaf(fmaxf(a1, 0.0f), sW3[cb + 2 * jj + 1], r3);
        }
    }

    out[oidx] = r3;
}

extern "C" void kernel_launch(void* const* d_in, const int* in_sizes, int n_in,
                              void* d_out, int out_size)
{
    const float* x    = (const float*)d_in[0];
    const float* tabs = (const float*)d_in[1];
    const float* res  = (const float*)d_in[2];
    const float* W1   = (const float*)d_in[3];
    const float* b1   = (const float*)d_in[4];
    const float* W2   = (const float*)d_in[5];
    const float* b2   = (const float*)d_in[6];
    const float* W3   = (const float*)d_in[7];
    const float* b3   = (const float*)d_in[8];
    float* out = (float*)d_out;

    const int n = in_sizes[0] / 3;

    k_zero<<<(NCELLS + 1023) / 1024, 1024>>>();
    k_hist<<<(n + 255) / 256, 256>>>(x, n);
    k_scan1<<<S1_B, S1_T>>>();
    k_scan2<<<1, S1_B>>>();
    k_scan3<<<S1_B, S1_T>>>();
    k_scatter<<<(n + 255) / 256, 256>>>(x, n);

    const int grid = (n + BLOCK - 1) / BLOCK;
    hashgrid_mlp_kernel<<<grid, BLOCK>>>(tabs, res, W1, b1, W2, b2, W3, b3, out, n);
}

// round 15
// speedup vs baseline: 2.7485x; 1.7013x over previous
#include <cuda_runtime.h>
#include <cstdint>

#define N_LEVELS 16
#define TABLE_SIZE (1u << 19)
#define TMASK (TABLE_SIZE - 1u)
#define P1 2654435761u
#define P2 805459861u
#define BLOCK 128
#define MAXN 2000000
#define GBITS 6
#define GRES (1 << GBITS)
#define NCELLS (GRES * GRES * GRES)  // 262144
#define S1_T 1024
#define S1_B (NCELLS / S1_T)         // 256

// ---- static scratch (no allocation) ----
__device__ int    d_hist[NCELLS];
__device__ int    d_offs[NCELLS];
__device__ int    d_bsum[S1_B];
__device__ int    d_boff[S1_B];
__device__ float4 d_xs[MAXN];

// ======================= sort pipeline (proven, R13) =======================
__device__ __forceinline__ unsigned part1by2(unsigned v) {
    v &= 0x3FFu;
    v = (v | (v << 16)) & 0x030000FFu;
    v = (v | (v << 8))  & 0x0300F00Fu;
    v = (v | (v << 4))  & 0x030C30C3u;
    v = (v | (v << 2))  & 0x09249249u;
    return v;
}
__device__ __forceinline__ int cell_of(float x0, float x1, float x2) {
    unsigned cx = min(GRES - 1, (int)(x0 * (float)GRES));
    unsigned cy = min(GRES - 1, (int)(x1 * (float)GRES));
    unsigned cz = min(GRES - 1, (int)(x2 * (float)GRES));
    return (int)((part1by2(cx) << 2) | (part1by2(cy) << 1) | part1by2(cz));
}
__global__ void k_zero() {
    int i = blockIdx.x * blockDim.x + threadIdx.x;
    if (i < NCELLS) d_hist[i] = 0;
}
__global__ void k_hist(const float* __restrict__ x, int n) {
    int i = blockIdx.x * blockDim.x + threadIdx.x;
    if (i >= n) return;
    float x0 = x[3*i+0]*0.5f+0.5f, x1 = x[3*i+1]*0.5f+0.5f, x2 = x[3*i+2]*0.5f+0.5f;
    atomicAdd(&d_hist[cell_of(x0, x1, x2)], 1);
}
__global__ void k_scan1() {
    __shared__ int sc[S1_T];
    const int t = threadIdx.x;
    const int g = blockIdx.x * S1_T + t;
    const int v = d_hist[g];
    sc[t] = v;
    __syncthreads();
    #pragma unroll
    for (int d = 1; d < S1_T; d <<= 1) {
        int u = (t >= d) ? sc[t - d] : 0;
        __syncthreads();
        sc[t] += u;
        __syncthreads();
    }
    d_offs[g] = sc[t] - v;
    if (t == S1_T - 1) d_bsum[blockIdx.x] = sc[t];
}
__global__ void k_scan2() {
    __shared__ int sc[S1_B];
    const int t = threadIdx.x;
    const int v = d_bsum[t];
    sc[t] = v;
    __syncthreads();
    #pragma unroll
    for (int d = 1; d < S1_B; d <<= 1) {
        int u = (t >= d) ? sc[t - d] : 0;
        __syncthreads();
        sc[t] += u;
        __syncthreads();
    }
    d_boff[t] = sc[t] - v;
}
__global__ void k_scan3() {
    const int g = blockIdx.x * S1_T + threadIdx.x;
    d_offs[g] += d_boff[blockIdx.x];
}
__global__ void k_scatter(const float* __restrict__ x, int n) {
    int i = blockIdx.x * blockDim.x + threadIdx.x;
    if (i >= n) return;
    float x0 = x[3*i+0]*0.5f+0.5f, x1 = x[3*i+1]*0.5f+0.5f, x2 = x[3*i+2]*0.5f+0.5f;
    int pos = atomicAdd(&d_offs[cell_of(x0, x1, x2)], 1);
    d_xs[pos] = make_float4(x0, x1, x2, __int_as_float(i));
}

// ======================= helpers =======================
__device__ __forceinline__ float tobf(float x) {
    float r;
    asm("{ .reg .b16 t; cvt.rn.bf16.f32 t, %1; cvt.f32.bf16 %0, t; }" : "=f"(r) : "f"(x));
    return r;
}
// pack {hi16 = a, lo16 = b}: low half = even column/k element
__device__ __forceinline__ uint32_t bfx2(float a, float b) {
    uint32_t r;
    asm("cvt.rn.bf16x2.f32 %0, %1, %2;" : "=r"(r) : "f"(a), "f"(b));
    return r;
}
// D(f32) += A(bf16,row) x B(bf16,col), m16n8k16 — baseline sm_80+ HMMA
__device__ __forceinline__ void mma16816(float* d, const uint32_t* a, const uint32_t* b) {
    asm volatile(
        "mma.sync.aligned.m16n8k16.row.col.f32.bf16.bf16.f32 "
        "{%0,%1,%2,%3}, {%4,%5,%6,%7}, {%8,%9}, {%0,%1,%2,%3};"
        : "+f"(d[0]), "+f"(d[1]), "+f"(d[2]), "+f"(d[3])
        : "r"(a[0]), "r"(a[1]), "r"(a[2]), "r"(a[3]), "r"(b[0]), "r"(b[1]));
}

#define A_STRIDE 20   // b32 per row (16 used), 16B-aligned, bank-conflict-free
#define B1_STRIDE 20  // [n][kcp<16]
#define B2_STRIDE 36  // [n][kcp<32], 4g+c banks: conflict-free

// ======================= fused encode + HMMA MLP =======================
__global__ __launch_bounds__(BLOCK, 3)
void hashgrid_mlp_kernel(const float* __restrict__ tables,
                         const float* __restrict__ resolutions,
                         const float* __restrict__ W1, const float* __restrict__ b1,
                         const float* __restrict__ W2, const float* __restrict__ b2,
                         const float* __restrict__ W3, const float* __restrict__ b3,
                         float* __restrict__ out, int n)
{
    // weights as bf16 hi/lo in fragment-friendly [n][k-pair] layouts
    __shared__ __align__(16) uint32_t smB1h[64 * B1_STRIDE];
    __shared__ __align__(16) uint32_t smB1l[64 * B1_STRIDE];
    __shared__ __align__(16) uint32_t smB2h[64 * B2_STRIDE];
    __shared__ __align__(16) uint32_t smB2l[64 * B2_STRIDE];
    // per-warp A1 staging: hi at [row*A_STRIDE+cp], lo at +32*A_STRIDE
    __shared__ __align__(16) uint32_t smA[4][2 * 32 * A_STRIDE];
    __shared__ float sB1b[64], sB2b[64], sW3v[64], sRes[16];
    __shared__ float sB3;

    const int tid = threadIdx.x;
    const int w   = tid >> 5;
    const int l   = tid & 31;
    const int g   = l >> 2;       // fragment row group
    const int c   = l & 3;        // fragment col group

    // ---- stage weights: [n][kcp] = pack(w[2kcp+1][n], w[2kcp][n]) ----
    for (int idx = tid; idx < 64 * 16; idx += BLOCK) {
        const int nn = idx & 63, kcp = idx >> 6;
        const float w0 = W1[(2 * kcp) * 64 + nn];
        const float w1 = W1[(2 * kcp + 1) * 64 + nn];
        const float h0 = tobf(w0), h1 = tobf(w1);
        smB1h[nn * B1_STRIDE + kcp] = bfx2(h1, h0);
        smB1l[nn * B1_STRIDE + kcp] = bfx2(w1 - h1, w0 - h0);
    }
    for (int idx = tid; idx < 64 * 32; idx += BLOCK) {
        const int nn = idx & 63, kcp = idx >> 6;
        const float w0 = W2[(2 * kcp) * 64 + nn];
        const float w1 = W2[(2 * kcp + 1) * 64 + nn];
        const float h0 = tobf(w0), h1 = tobf(w1);
        smB2h[nn * B2_STRIDE + kcp] = bfx2(h1, h0);
        smB2l[nn * B2_STRIDE + kcp] = bfx2(w1 - h1, w0 - h0);
    }
    if (tid < 64) { sB1b[tid] = b1[tid]; sB2b[tid] = b2[tid]; sW3v[tid] = W3[tid]; }
    if (tid < 16) sRes[tid] = resolutions[tid];
    if (tid == 0) sB3 = b3[0];
    __syncthreads();

    const int tileBase = blockIdx.x * BLOCK + w * 32;   // warp-local rows 0..31
    const int p = tileBase + l;
    const bool act = p < n;
    const float4 xi = d_xs[act ? p : (n - 1)];
    const float x0 = xi.x, x1 = xi.y, x2 = xi.z;
    const int oidx = __float_as_int(xi.w);

    // ---- encode (proven) ----
    float a[32];
    #pragma unroll
    for (int L = 0; L < N_LEVELS; L++) {
        const float r = sRes[L];
        const float px = x0 * r, py = x1 * r, pz = x2 * r;
        const float fx = floorf(px), fy = floorf(py), fz = floorf(pz);
        const float wx = px - fx, wy = py - fy, wz = pz - fz;
        const unsigned cx = (unsigned)fx, cy = (unsigned)fy, cz = (unsigned)fz;
        const unsigned hx0 = cx,      hx1 = cx + 1u;
        const unsigned hy0 = cy * P1, hy1 = (cy + 1u) * P1;
        const unsigned hz0 = cz * P2, hz1 = (cz + 1u) * P2;
        const float2* __restrict__ tab =
            reinterpret_cast<const float2*>(tables) + (size_t)L * TABLE_SIZE;
        const float ox = 1.0f - wx, oy = 1.0f - wy, oz = 1.0f - wz;
        float ax = 0.0f, ay = 0.0f;
        #pragma unroll
        for (int cc = 0; cc < 8; cc++) {
            const unsigned h = ((cc & 1) ? hx1 : hx0) ^ ((cc & 2) ? hy1 : hy0)
                             ^ ((cc & 4) ? hz1 : hz0);
            const float2 tv = __ldg(&tab[h & TMASK]);
            const float wc = ((cc & 1) ? wx : ox) * ((cc & 2) ? wy : oy)
                           * ((cc & 4) ? wz : oz);
            ax = fmaf(wc, tv.x, ax);
            ay = fmaf(wc, tv.y, ay);
        }
        a[2 * L + 0] = ax;
        a[2 * L + 1] = ay;
    }

    // ---- A1 -> per-warp smem as bf16 hi/lo (row = warp-local point = l) ----
    {
        uint32_t ph[16], pl[16];
        #pragma unroll
        for (int cp = 0; cp < 16; cp++) {
            const float v0 = a[2 * cp], v1 = a[2 * cp + 1];
            const float h0 = tobf(v0), h1 = tobf(v1);
            ph[cp] = bfx2(h1, h0);
            pl[cp] = bfx2(v1 - h1, v0 - h0);
        }
        uint32_t* rowh = &smA[w][l * A_STRIDE];
        uint32_t* rowl = &smA[w][32 * A_STRIDE + l * A_STRIDE];
        #pragma unroll
        for (int i = 0; i < 4; i++) {
            *reinterpret_cast<uint4*>(rowh + 4 * i) =
                make_uint4(ph[4*i], ph[4*i+1], ph[4*i+2], ph[4*i+3]);
            *reinterpret_cast<uint4*>(rowl + 4 * i) =
                make_uint4(pl[4*i], pl[4*i+1], pl[4*i+2], pl[4*i+3]);
        }
    }
    __syncwarp();

    // ---- load A1 fragments ----
    uint32_t a1h[2][2][4], a1l[2][2][4];
    {
        const uint32_t* basen = &smA[w][0];
        #pragma unroll
        for (int mt = 0; mt < 2; mt++)
            #pragma unroll
            for (int kt = 0; kt < 2; kt++) {
                const int r0 = mt * 16 + g, r1 = r0 + 8;
                const int cp0 = kt * 8 + c;
                a1h[mt][kt][0] = basen[r0 * A_STRIDE + cp0];
                a1h[mt][kt][1] = basen[r1 * A_STRIDE + cp0];
                a1h[mt][kt][2] = basen[r0 * A_STRIDE + cp0 + 4];
                a1h[mt][kt][3] = basen[r1 * A_STRIDE + cp0 + 4];
                a1l[mt][kt][0] = basen[32 * A_STRIDE + r0 * A_STRIDE + cp0];
                a1l[mt][kt][1] = basen[32 * A_STRIDE + r1 * A_STRIDE + cp0];
                a1l[mt][kt][2] = basen[32 * A_STRIDE + r0 * A_STRIDE + cp0 + 4];
                a1l[mt][kt][3] = basen[32 * A_STRIDE + r1 * A_STRIDE + cp0 + 4];
            }
    }

    // ---- layer 1: D1[32x64] = A1 @ W1 (3-term bf16 split) ----
    float d1[2][8][4];
    #pragma unroll
    for (int mt = 0; mt < 2; mt++)
        #pragma unroll
        for (int nt = 0; nt < 8; nt++)
            #pragma unroll
            for (int r = 0; r < 4; r++) d1[mt][nt][r] = 0.0f;

    #pragma unroll
    for (int nt = 0; nt < 8; nt++) {
        uint32_t bh[2][2], bl[2][2];
        #pragma unroll
        for (int kt = 0; kt < 2; kt++) {
            const int nrow = nt * 8 + g;
            bh[kt][0] = smB1h[nrow * B1_STRIDE + kt * 8 + c];
            bh[kt][1] = smB1h[nrow * B1_STRIDE + kt * 8 + c + 4];
            bl[kt][0] = smB1l[nrow * B1_STRIDE + kt * 8 + c];
            bl[kt][1] = smB1l[nrow * B1_STRIDE + kt * 8 + c + 4];
        }
        #pragma unroll
        for (int mt = 0; mt < 2; mt++)
            #pragma unroll
            for (int kt = 0; kt < 2; kt++) {
                mma16816(d1[mt][nt], a1h[mt][kt], bh[kt]);
                mma16816(d1[mt][nt], a1l[mt][kt], bh[kt]);
                mma16816(d1[mt][nt], a1h[mt][kt], bl[kt]);
            }
    }

    // ---- epilogue1: relu(D1+b1) -> A2 fragments DIRECTLY in registers ----
    uint32_t a2h[2][4][4], a2l[2][4][4];
    #pragma unroll
    for (int mt = 0; mt < 2; mt++)
        #pragma unroll
        for (int nt = 0; nt < 8; nt++) {
            const float2 bp = *reinterpret_cast<const float2*>(&sB1b[nt * 8 + 2 * c]);
            const float f0 = fmaxf(d1[mt][nt][0] + bp.x, 0.0f);
            const float f1 = fmaxf(d1[mt][nt][1] + bp.y, 0.0f);
            const float f2 = fmaxf(d1[mt][nt][2] + bp.x, 0.0f);
            const float f3 = fmaxf(d1[mt][nt][3] + bp.y, 0.0f);
            const float h0 = tobf(f0), h1 = tobf(f1), h2 = tobf(f2), h3 = tobf(f3);
            const int kt2 = nt >> 1, rb = (nt & 1) * 2;
            a2h[mt][kt2][rb + 0] = bfx2(h1, h0);
            a2h[mt][kt2][rb + 1] = bfx2(h3, h2);
            a2l[mt][kt2][rb + 0] = bfx2(f1 - h1, f0 - h0);
            a2l[mt][kt2][rb + 1] = bfx2(f3 - h3, f2 - h2);
        }

    // ---- layer 2 (two N-halves) fused with layer-3 dot ----
    float s[2][2] = {{0.0f, 0.0f}, {0.0f, 0.0f}};
    #pragma unroll
    for (int half = 0; half < 2; half++) {
        float d2[2][4][4];
        #pragma unroll
        for (int mt = 0; mt < 2; mt++)
            #pragma unroll
            for (int ntl = 0; ntl < 4; ntl++)
                #pragma unroll
                for (int r = 0; r < 4; r++) d2[mt][ntl][r] = 0.0f;

        #pragma unroll
        for (int ntl = 0; ntl < 4; ntl++) {
            const int nt = half * 4 + ntl;
            uint32_t bh[4][2], bl[4][2];
            #pragma unroll
            for (int kt = 0; kt < 4; kt++) {
                const int nrow = nt * 8 + g;
                bh[kt][0] = smB2h[nrow * B2_STRIDE + kt * 8 + c];
                bh[kt][1] = smB2h[nrow * B2_STRIDE + kt * 8 + c + 4];
                bl[kt][0] = smB2l[nrow * B2_STRIDE + kt * 8 + c];
                bl[kt][1] = smB2l[nrow * B2_STRIDE + kt * 8 + c + 4];
            }
            #pragma unroll
            for (int mt = 0; mt < 2; mt++)
                #pragma unroll
                for (int kt = 0; kt < 4; kt++) {
                    mma16816(d2[mt][ntl], a2h[mt][kt], bh[kt]);
                    mma16816(d2[mt][ntl], a2l[mt][kt], bh[kt]);
                    mma16816(d2[mt][ntl], a2h[mt][kt], bl[kt]);
                }
        }
        #pragma unroll
        for (int mt = 0; mt < 2; mt++)
            #pragma unroll
            for (int ntl = 0; ntl < 4; ntl++) {
                const int col = (half * 4 + ntl) * 8 + 2 * c;
                const float2 bp = *reinterpret_cast<const float2*>(&sB2b[col]);
                const float2 wp = *reinterpret_cast<const float2*>(&sW3v[col]);
                s[mt][0] += fmaxf(d2[mt][ntl][0] + bp.x, 0.0f) * wp.x
                          + fmaxf(d2[mt][ntl][1] + bp.y, 0.0f) * wp.y;
                s[mt][1] += fmaxf(d2[mt][ntl][2] + bp.x, 0.0f) * wp.x
                          + fmaxf(d2[mt][ntl][3] + bp.y, 0.0f) * wp.y;
            }
    }

    // ---- quad reduce + scatter store ----
    #pragma unroll
    for (int mt = 0; mt < 2; mt++)
        #pragma unroll
        for (int r = 0; r < 2; r++) {
            float v = s[mt][r];
            v += __shfl_xor_sync(0xFFFFFFFFu, v, 1);
            v += __shfl_xor_sync(0xFFFFFFFFu, v, 2);
            const int q = mt * 16 + g + r * 8;          // warp-local row
            const int oi = __shfl_sync(0xFFFFFFFFu, oidx, q);
            if (c == 0 && (tileBase + q) < n) out[oi] = v + sB3;
        }
}

extern "C" void kernel_launch(void* const* d_in, const int* in_sizes, int n_in,
                              void* d_out, int out_size)
{
    const float* x    = (const float*)d_in[0];
    const float* tabs = (const float*)d_in[1];
    const float* res  = (const float*)d_in[2];
    const float* W1   = (const float*)d_in[3];
    const float* b1   = (const float*)d_in[4];
    const float* W2   = (const float*)d_in[5];
    const float* b2   = (const float*)d_in[6];
    const float* W3   = (const float*)d_in[7];
    const float* b3   = (const float*)d_in[8];
    float* out = (float*)d_out;

    const int n = in_sizes[0] / 3;

    k_zero<<<(NCELLS + 1023) / 1024, 1024>>>();
    k_hist<<<(n + 255) / 256, 256>>>(x, n);
    k_scan1<<<S1_B, S1_T>>>();
    k_scan2<<<1, S1_B>>>();
    k_scan3<<<S1_B, S1_T>>>();
    k_scatter<<<(n + 255) / 256, 256>>>(x, n);

    const int grid = (n + BLOCK - 1) / BLOCK;
    hashgrid_mlp_kernel<<<grid, BLOCK>>>(tabs, res, W1, b1, W2, b2, W3, b3, out, n);
}